// round 11
// baseline (speedup 1.0000x reference)
#include <cuda_runtime.h>
#include <cstdint>

namespace {

constexpr int T_ = 128, H_ = 16, N_ = 64, C_ = 256, S_ = 129;
constexpr int NC_ = N_ * C_;
constexpr int NPROD = 31;          // producers per n: 15 (rank0) + 16 (rank1)

constexpr float L2E     = 1.4426950408889634f;
constexpr float LN2     = 0.6931471805599453f;
constexpr float MINF    = 1.17549435e-38f;     // 2^-126 == FLT_MIN == TINY
constexpr float NEG_BIG = -1e30f;

__device__ __forceinline__ float ex2f(float x) { float y; asm("ex2.approx.f32 %0, %1;" : "=f"(y) : "f"(x)); return y; }
__device__ __forceinline__ float lg2f(float x) { float y; asm("lg2.approx.f32 %0, %1;" : "=f"(y) : "f"(x)); return y; }

__device__ __forceinline__ uint32_t smem_u32(const void* p) {
    uint32_t a;
    asm("{ .reg .u64 t; cvta.to.shared.u64 t, %1; cvt.u32.u64 %0, t; }" : "=r"(a) : "l"(p));
    return a;
}
__device__ __forceinline__ uint32_t mapa_rank0(uint32_t local) {
    uint32_t r;
    asm("mapa.shared::cluster.u32 %0, %1, 0;" : "=r"(r) : "r"(local));
    return r;
}
__device__ __forceinline__ void st_cl_f32(uint32_t a, float v) {
    asm volatile("st.shared::cluster.f32 [%0], %1;" :: "r"(a), "f"(v));
}
__device__ __forceinline__ void mbar_init(uint32_t a, unsigned cnt) {
    asm volatile("mbarrier.init.shared.b64 [%0], %1;" :: "r"(a), "r"(cnt) : "memory");
}
__device__ __forceinline__ void mbar_arrive_cluster(uint32_t mapped) {
    asm volatile("mbarrier.arrive.release.cluster.shared::cluster.b64 _, [%0];"
                 :: "r"(mapped) : "memory");
}
__device__ __forceinline__ void mbar_wait0(uint32_t a) {
    uint32_t done;
    asm volatile(
        "{\n\t.reg .pred p;\n\t"
        "mbarrier.try_wait.parity.acquire.cta.shared::cta.b64 p, [%1], 0;\n\t"
        "selp.b32 %0, 1, 0, p;\n\t}"
        : "=r"(done) : "r"(a) : "memory");
    if (!done) {
        asm volatile(
            "{\n\t.reg .pred P1;\n\t"
            "WL_%=:\n\t"
            "mbarrier.try_wait.parity.acquire.cta.shared::cta.b64 P1, [%0], 0, 0x989680;\n\t"
            "@P1 bra.uni WD_%=;\n\t"
            "bra.uni WL_%=;\n\t"
            "WD_%=:\n\t}"
            :: "r"(a) : "memory");
    }
}
__device__ __forceinline__ void cluster_sync() {
    asm volatile("barrier.cluster.arrive.aligned;" ::: "memory");
    asm volatile("barrier.cluster.wait.aligned;" ::: "memory");
}
__device__ __forceinline__ uint32_t ctarank() {
    uint32_t r; asm("mov.u32 %0, %%cluster_ctarank;" : "=r"(r)); return r;
}

// 2-CTA cluster per n, 512 threads/CTA. Rank0: 15 producer warps + consumer
// warp 15; rank1: 16 producers. Producer: 8-deep x 2 LDG.128 register pipeline
// with cross-row prefetch (16 outstanding loads/warp); computes ex2 for all
// 256 columns, accumulates over h, writes lg2 of the needed deduped columns
// into rank0's G row (per-lane ownership table), per-lane release-arrive on
// the row mbarrier. Consumer acquire-waits per row, serial CTC recurrence.
__global__ __launch_bounds__(512, 1) __cluster_dims__(2, 1, 1)
void fused_kernel(
    const float* __restrict__ mask,      // [T,H,N]
    const float* __restrict__ classify,  // [T,H,N,C]
    const int*   __restrict__ targets,   // [N,64]
    const int*   __restrict__ tlen,      // [N]
    float* __restrict__ out)             // [N]
{
    __shared__ float    G_sh[T_][68];
    __shared__ uint64_t mbar[T_];
    __shared__ int      tgt_sh[64];
    __shared__ int      cc_sh[T_];
    __shared__ float    res_sh[S_];
    __shared__ uint16_t ent[32][66];   // per-lane (c_idx<<4 | k) entries
    __shared__ int      cnt[32];

    const int n    = blockIdx.x >> 1;
    const int rank = (int)ctarank();
    const int tid  = threadIdx.x;
    const int w    = tid >> 5;
    const int lane = tid & 31;

    if (rank == 0 && tid < T_) mbar_init(smem_u32(&mbar[tid]), 32);
    if (tid < 64) tgt_sh[tid] = targets[n * 64 + tid];
    __syncthreads();

    // build column->lane ownership table (once per CTA)
    if (tid == 0) {
#pragma unroll
        for (int l = 0; l < 32; ++l) cnt[l] = 0;
        for (int c = 0; c < 65; ++c) {
            const int v     = (c == 0) ? 0 : tgt_sh[c - 1];
            const int owner = (v & 127) >> 2;
            const int k     = (v & 3) | ((v >= 128) ? 4 : 0);
            ent[owner][cnt[owner]++] = (uint16_t)((c << 4) | k);
        }
    }
    __syncthreads();
    cluster_sync();                 // barriers + tables live before producing

    const bool isProd = (rank == 1) || (w < 15);

    if (isProd) {
        // ======================= producer warp =======================
        const int pid = (rank == 0) ? w : (15 + w);   // 0..30
        const int nt  = (pid < 4) ? 5 : 4;            // rows: t = pid + 31*i
        const int cn  = cnt[lane];
        uint16_t  el[8];
#pragma unroll
        for (int i = 0; i < 8; ++i) el[i] = (i < cn) ? ent[lane][i] : 0;
        const bool spill = (cn > 8);

        const float* cbase = classify + (size_t)n * C_ + 4 * lane;

        // mask for row 0 (lane<16 holds mask[t, h=lane]); pre-scaled by L2E
        float mcur = (lane < 16) ? __ldg(&mask[((size_t)pid * H_ + lane) * N_ + n]) * L2E : 0.f;
        float mnext = 0.f;

        // 8-deep x 2 LDG.128 pipeline; slot for (row i, h) = h & 7
        float4 A[8], B[8];
#pragma unroll
        for (int h = 0; h < 8; ++h) {
            const float* r = cbase + ((size_t)pid * H_ + h) * NC_;
            A[h] = *reinterpret_cast<const float4*>(r);
            B[h] = *reinterpret_cast<const float4*>(r + 128);
        }

        for (int i = 0; i < nt; ++i) {
            const int t = pid + 31 * i;
            float acc0 = 0.f, acc1 = 0.f, acc2 = 0.f, acc3 = 0.f;
            float acc4 = 0.f, acc5 = 0.f, acc6 = 0.f, acc7 = 0.f;
#pragma unroll
            for (int h = 0; h < H_; ++h) {
                const int    slot = h & 7;
                const float4 a = A[slot], bb = B[slot];
                // prefetch: h<8 -> (i, h+8); h>=8 -> (i+1, h-8)
                if (h < 8) {
                    const float* r = cbase + ((size_t)t * H_ + (h + 8)) * NC_;
                    A[slot] = *reinterpret_cast<const float4*>(r);
                    B[slot] = *reinterpret_cast<const float4*>(r + 128);
                } else if (i + 1 < nt) {
                    const float* r = cbase + ((size_t)(t + 31) * H_ + (h - 8)) * NC_;
                    A[slot] = *reinterpret_cast<const float4*>(r);
                    B[slot] = *reinterpret_cast<const float4*>(r + 128);
                }
                if (h == 0 && i + 1 < nt && lane < 16)
                    mnext = __ldg(&mask[((size_t)(t + 31) * H_ + lane) * N_ + n]) * L2E;

                const float mh = __shfl_sync(0xffffffffu, mcur, h);
                acc0 += ex2f(__fmaf_rn(a.x,  L2E, mh));
                acc1 += ex2f(__fmaf_rn(a.y,  L2E, mh));
                acc2 += ex2f(__fmaf_rn(a.z,  L2E, mh));
                acc3 += ex2f(__fmaf_rn(a.w,  L2E, mh));
                acc4 += ex2f(__fmaf_rn(bb.x, L2E, mh));
                acc5 += ex2f(__fmaf_rn(bb.y, L2E, mh));
                acc6 += ex2f(__fmaf_rn(bb.z, L2E, mh));
                acc7 += ex2f(__fmaf_rn(bb.w, L2E, mh));
            }

            // write needed columns of row t into rank0's G_sh, then arrive
            const uint32_t r0 = mapa_rank0(smem_u32(&G_sh[t][0]));
            const int nreg = spill ? 8 : cn;
#pragma unroll
            for (int q = 0; q < 8; ++q) {
                if (q < nreg) {
                    const int u = el[q];
                    const int k = u & 7;
                    float s = (k == 0) ? acc0 : (k == 1) ? acc1 : (k == 2) ? acc2 :
                              (k == 3) ? acc3 : (k == 4) ? acc4 : (k == 5) ? acc5 :
                              (k == 6) ? acc6 : acc7;
                    st_cl_f32(r0 + 4u * (u >> 4), lg2f(s));
                }
            }
            if (spill) {
                for (int q = 8; q < cn; ++q) {
                    const int u = ent[lane][q];
                    const int k = u & 7;
                    float s = (k == 0) ? acc0 : (k == 1) ? acc1 : (k == 2) ? acc2 :
                              (k == 3) ? acc3 : (k == 4) ? acc4 : (k == 5) ? acc5 :
                              (k == 6) ? acc6 : acc7;
                    st_cl_f32(r0 + 4u * (u >> 4), lg2f(s));
                }
            }
            mbar_arrive_cluster(mapa_rank0(smem_u32(&mbar[t])));
            mcur = mnext;
        }
        return;
    }

    // =================== consumer warp (rank0, w == 15) ===================
    const int NS = (lane == 31) ? 5 : 4;
    const int sB = 4 * lane;

    // cc prefix scan (reachability frontier)
    {
        int c[4], pfx = 0;
#pragma unroll
        for (int i = 0; i < 4; ++i) {
            int u = 4 * lane + i, v = 0;
            if (u >= 2) {
                int sk = 0;
                if ((u & 1) && u >= 3) sk = (tgt_sh[(u - 1) >> 1] != tgt_sh[(u - 3) >> 1]);
                v = sk + 1;
            }
            pfx += v; c[i] = pfx;
        }
        int tot = pfx;
#pragma unroll
        for (int d = 1; d < 32; d <<= 1) {
            int up = __shfl_up_sync(0xffffffffu, tot, d);
            if (lane >= d) tot += up;
        }
        int excl = tot - pfx;
#pragma unroll
        for (int i = 0; i < 4; ++i) {
            int u = 4 * lane + i;
            if (u >= 1) cc_sh[u] = 2 + excl + c[i];
        }
    }
    __syncwarp();

    bool skipb[5];
#pragma unroll
    for (int i = 0; i < 5; ++i) {
        int s = sB + i;
        skipb[i] = (i < NS) && (s & 1) && (s >= 3) &&
                   (tgt_sh[(s - 1) >> 1] != tgt_sh[(s - 3) >> 1]);
    }

    const int cO1 = 2 * lane + 1;
    const int cO2 = 2 * lane + 2;

    float np[5];
#pragma unroll
    for (int i = 0; i < 5; ++i) np[i] = (sB + i < 2) ? 0.f : NEG_BIG;

    mbar_wait0(smem_u32(&mbar[0]));
    float gE = G_sh[0][0], gO1 = G_sh[0][cO1], gO2 = G_sh[0][cO2];

    for (int t = 1; t < T_; ++t) {
        mbar_wait0(smem_u32(&mbar[t]));
        const float aE = G_sh[t][0], aO1 = G_sh[t][cO1], aO2 = G_sh[t][cO2];
        const int cc_t = cc_sh[t];

        // E-domain step: E = max(ex2(np+g), 2^-126)  [== reference's TINY clamp]
        float e[5];
        e[0] = fmaxf(ex2f(np[0] + gE),  MINF);
        e[1] = fmaxf(ex2f(np[1] + gO1), MINF);
        e[2] = fmaxf(ex2f(np[2] + gE),  MINF);
        e[3] = fmaxf(ex2f(np[3] + gO2), MINF);
        e[4] = fmaxf(ex2f(np[4] + gE),  MINF);
#pragma unroll
        for (int i = 0; i < 5; ++i)
            if (sB + i > cc_t) e[i] = MINF;

        const float em1 = __shfl_up_sync(0xffffffffu, e[3], 1);
        const float em2 = __shfl_up_sync(0xffffffffu, e[2], 1);

        np[0] = (lane == 0) ? lg2f(e[0])
                            : lg2f(e[0] + em1 + (skipb[0] ? em2 : 0.f));
        np[1] = lg2f(e[1] + e[0] + (skipb[1] ? em1 : 0.f));
#pragma unroll
        for (int i = 2; i < 5; ++i)
            np[i] = lg2f(e[i] + e[i - 1] + (skipb[i] ? e[i - 2] : 0.f));

        gE = aE; gO1 = aO1; gO2 = aO2;
    }

    // final: res2[s] = np2[s] + G2[127][s]
    res_sh[sB + 0] = np[0] + gE;
    res_sh[sB + 1] = np[1] + gO1;
    res_sh[sB + 2] = np[2] + gE;
    res_sh[sB + 3] = np[3] + gO2;
    if (lane == 31) res_sh[128] = np[4] + gE;
    __syncwarp();

    if (lane == 0) {
        const int   L = 2 * tlen[n] + 1;
        const float x = res_sh[L - 1], y = res_sh[L - 2];
        const float mx = fmaxf(x, y);
        const float l2 = mx + lg2f(ex2f(x - mx) + ex2f(y - mx));
        out[n] = -((LN2 * l2) / (float)tlen[n]);
    }
}

} // anonymous namespace

extern "C" void kernel_launch(void* const* d_in, const int* /*in_sizes*/, int /*n_in*/,
                              void* d_out, int /*out_size*/) {
    const float* mask     = (const float*)d_in[0];
    const float* classify = (const float*)d_in[1];
    const int*   targets  = (const int*)d_in[2];
    // d_in[3] = input_lengths (always T, unused)
    const int*   tlen     = (const int*)d_in[4];

    fused_kernel<<<2 * N_, 512>>>(mask, classify, targets, tlen, (float*)d_out);
}

// round 12
// speedup vs baseline: 1.1437x; 1.1437x over previous
#include <cuda_runtime.h>
#include <cstdint>

namespace {

constexpr int T_ = 128, H_ = 16, N_ = 64, C_ = 256, S_ = 129;
constexpr int NC_ = N_ * C_;
constexpr int NPROD = 31;          // producers per n: 15 (rank0) + 16 (rank1)

constexpr float L2E  = 1.4426950408889634f;
constexpr float LN2  = 0.6931471805599453f;
constexpr float MINF = 1.17549435e-38f;        // 2^-126 == FLT_MIN == TINY

__device__ __forceinline__ float ex2f(float x) { float y; asm("ex2.approx.f32 %0, %1;" : "=f"(y) : "f"(x)); return y; }
__device__ __forceinline__ float lg2f(float x) { float y; asm("lg2.approx.f32 %0, %1;" : "=f"(y) : "f"(x)); return y; }

__device__ __forceinline__ uint32_t smem_u32(const void* p) {
    uint32_t a;
    asm("{ .reg .u64 t; cvta.to.shared.u64 t, %1; cvt.u32.u64 %0, t; }" : "=r"(a) : "l"(p));
    return a;
}
__device__ __forceinline__ uint32_t mapa_rank0(uint32_t local) {
    uint32_t r;
    asm("mapa.shared::cluster.u32 %0, %1, 0;" : "=r"(r) : "r"(local));
    return r;
}
__device__ __forceinline__ void st_cl_f32(uint32_t a, float v) {
    asm volatile("st.shared::cluster.f32 [%0], %1;" :: "r"(a), "f"(v));
}
__device__ __forceinline__ void mbar_init(uint32_t a, unsigned cnt) {
    asm volatile("mbarrier.init.shared.b64 [%0], %1;" :: "r"(a), "r"(cnt) : "memory");
}
__device__ __forceinline__ void mbar_arrive_cluster(uint32_t mapped) {
    asm volatile("mbarrier.arrive.release.cluster.shared::cluster.b64 _, [%0];"
                 :: "r"(mapped) : "memory");
}
__device__ __forceinline__ void mbar_wait0(uint32_t a) {
    uint32_t done;
    asm volatile(
        "{\n\t.reg .pred p;\n\t"
        "mbarrier.try_wait.parity.acquire.cta.shared::cta.b64 p, [%1], 0;\n\t"
        "selp.b32 %0, 1, 0, p;\n\t}"
        : "=r"(done) : "r"(a) : "memory");
    if (!done) {
        asm volatile(
            "{\n\t.reg .pred P1;\n\t"
            "WL_%=:\n\t"
            "mbarrier.try_wait.parity.acquire.cta.shared::cta.b64 P1, [%0], 0, 0x989680;\n\t"
            "@P1 bra.uni WD_%=;\n\t"
            "bra.uni WL_%=;\n\t"
            "WD_%=:\n\t}"
            :: "r"(a) : "memory");
    }
}
__device__ __forceinline__ void cluster_sync() {
    asm volatile("barrier.cluster.arrive.aligned;" ::: "memory");
    asm volatile("barrier.cluster.wait.aligned;" ::: "memory");
}
__device__ __forceinline__ uint32_t ctarank() {
    uint32_t r; asm("mov.u32 %0, %%cluster_ctarank;" : "=r"(r)); return r;
}

// 2-CTA cluster per n, 512 threads/CTA. Rank0: 15 producer warps + consumer
// warp 15; rank1: 16 producers. Producers load full classify rows coalesced
// (float4, depth-4 pipeline), compute LINEAR S[t][c] = sum_h 2^(cls+m) for the
// 65 deduped columns (per-lane ownership table), write into rank0's smem via
// DSMEM, and release-arrive on the row-GROUP (4 rows) mbarrier. Consumer
// acquire-waits per group and runs the CTC recurrence fully in the linear
// domain: e = max(P*S, TINY)  ==  exp(log(max(sum, TINY))) of the reference.
__global__ __launch_bounds__(512, 1) __cluster_dims__(2, 1, 1)
void fused_kernel(
    const float* __restrict__ mask,      // [T,H,N]
    const float* __restrict__ classify,  // [T,H,N,C]
    const int*   __restrict__ targets,   // [N,64]
    const int*   __restrict__ tlen,      // [N]
    float* __restrict__ out)             // [N]
{
    __shared__ float    S_sh[T_][68];    // linear per-column h-sums
    __shared__ uint64_t mbar[T_ / 4];    // one barrier per 4-row group
    __shared__ int      tgt_sh[64];
    __shared__ int      cc_sh[T_];
    __shared__ float    res_sh[S_];
    __shared__ uint16_t ent[32][66];     // per-lane (c_idx<<4 | k) entries
    __shared__ int      cnt[32];

    const int n    = blockIdx.x >> 1;
    const int rank = (int)ctarank();
    const int tid  = threadIdx.x;
    const int w    = tid >> 5;
    const int lane = tid & 31;

    if (rank == 0 && tid < T_ / 4) mbar_init(smem_u32(&mbar[tid]), 128);
    if (tid < 64) tgt_sh[tid] = targets[n * 64 + tid];
    __syncthreads();

    // build column->lane ownership table (once per CTA)
    if (tid == 0) {
#pragma unroll
        for (int l = 0; l < 32; ++l) cnt[l] = 0;
        for (int c = 0; c < 65; ++c) {
            const int v     = (c == 0) ? 0 : tgt_sh[c - 1];
            const int owner = (v & 127) >> 2;
            const int k     = (v & 3) | ((v >= 128) ? 4 : 0);
            ent[owner][cnt[owner]++] = (uint16_t)((c << 4) | k);
        }
    }
    __syncthreads();
    cluster_sync();                 // barriers + tables live before producing

    const bool isProd = (rank == 1) || (w < 15);

    if (isProd) {
        // ======================= producer warp =======================
        const int pid = (rank == 0) ? w : (15 + w);   // 0..30
        const int cn  = cnt[lane];
        uint16_t  el[8];
#pragma unroll
        for (int i = 0; i < 8; ++i) el[i] = (i < cn) ? ent[lane][i] : 0;
        const bool spill = (cn > 8);

        for (int t = pid; t < T_; t += NPROD) {
            const float* b0 = classify + ((size_t)t * H_ * N_ + n) * C_;
            const float  m  = (lane < 16)
                ? __ldg(&mask[((size_t)t * H_ + lane) * N_ + n]) * L2E : 0.f;

            // depth-4 register pipeline over h
            float4 A[4], B[4];
#pragma unroll
            for (int j = 0; j < 4; ++j) {
                const float* r = b0 + (size_t)j * NC_;
                A[j] = *reinterpret_cast<const float4*>(r + 4 * lane);
                B[j] = *reinterpret_cast<const float4*>(r + 128 + 4 * lane);
            }

            float acc0 = 0.f, acc1 = 0.f, acc2 = 0.f, acc3 = 0.f;
            float acc4 = 0.f, acc5 = 0.f, acc6 = 0.f, acc7 = 0.f;
#pragma unroll
            for (int h = 0; h < H_; ++h) {
                const int    slot = h & 3;
                const float4 a = A[slot], bb = B[slot];
                if (h + 4 < H_) {
                    const float* r = b0 + (size_t)(h + 4) * NC_;
                    A[slot] = *reinterpret_cast<const float4*>(r + 4 * lane);
                    B[slot] = *reinterpret_cast<const float4*>(r + 128 + 4 * lane);
                }
                const float mh = __shfl_sync(0xffffffffu, m, h);
                acc0 += ex2f(__fmaf_rn(a.x,  L2E, mh));
                acc1 += ex2f(__fmaf_rn(a.y,  L2E, mh));
                acc2 += ex2f(__fmaf_rn(a.z,  L2E, mh));
                acc3 += ex2f(__fmaf_rn(a.w,  L2E, mh));
                acc4 += ex2f(__fmaf_rn(bb.x, L2E, mh));
                acc5 += ex2f(__fmaf_rn(bb.y, L2E, mh));
                acc6 += ex2f(__fmaf_rn(bb.z, L2E, mh));
                acc7 += ex2f(__fmaf_rn(bb.w, L2E, mh));
            }

            // write needed LINEAR sums of row t into rank0's S_sh
            const uint32_t r0 = mapa_rank0(smem_u32(&S_sh[t][0]));
            const int nreg = spill ? 8 : cn;
#pragma unroll
            for (int q = 0; q < 8; ++q) {
                if (q < nreg) {
                    const int u = el[q];
                    const int k = u & 7;
                    float s = (k == 0) ? acc0 : (k == 1) ? acc1 : (k == 2) ? acc2 :
                              (k == 3) ? acc3 : (k == 4) ? acc4 : (k == 5) ? acc5 :
                              (k == 6) ? acc6 : acc7;
                    st_cl_f32(r0 + 4u * (u >> 4), s);
                }
            }
            if (spill) {
                for (int q = 8; q < cn; ++q) {
                    const int u = ent[lane][q];
                    const int k = u & 7;
                    float s = (k == 0) ? acc0 : (k == 1) ? acc1 : (k == 2) ? acc2 :
                              (k == 3) ? acc3 : (k == 4) ? acc4 : (k == 5) ? acc5 :
                              (k == 6) ? acc6 : acc7;
                    st_cl_f32(r0 + 4u * (u >> 4), s);
                }
            }
            // per-lane release-arrive on the row's GROUP barrier
            mbar_arrive_cluster(mapa_rank0(smem_u32(&mbar[t >> 2])));
        }
        return;
    }

    // =================== consumer warp (rank0, w == 15) ===================
    const int NS = (lane == 31) ? 5 : 4;
    const int sB = 4 * lane;

    // cc prefix scan (reachability frontier)
    {
        int c[4], pfx = 0;
#pragma unroll
        for (int i = 0; i < 4; ++i) {
            int u = 4 * lane + i, v = 0;
            if (u >= 2) {
                int sk = 0;
                if ((u & 1) && u >= 3) sk = (tgt_sh[(u - 1) >> 1] != tgt_sh[(u - 3) >> 1]);
                v = sk + 1;
            }
            pfx += v; c[i] = pfx;
        }
        int tot = pfx;
#pragma unroll
        for (int d = 1; d < 32; d <<= 1) {
            int up = __shfl_up_sync(0xffffffffu, tot, d);
            if (lane >= d) tot += up;
        }
        int excl = tot - pfx;
#pragma unroll
        for (int i = 0; i < 4; ++i) {
            int u = 4 * lane + i;
            if (u >= 1) cc_sh[u] = 2 + excl + c[i];
        }
    }
    __syncwarp();

    bool skipb[5];
#pragma unroll
    for (int i = 0; i < 5; ++i) {
        int s = sB + i;
        skipb[i] = (i < NS) && (s & 1) && (s >= 3) &&
                   (tgt_sh[(s - 1) >> 1] != tgt_sh[(s - 3) >> 1]);
    }

    const int cO1 = 2 * lane + 1;   // col of state 4l+1
    const int cO2 = 2 * lane + 2;   // col of state 4l+3

    // linear-domain state: P[i] = 2^np[i]
    float P[5];
#pragma unroll
    for (int i = 0; i < 5; ++i) P[i] = (sB + i < 2) ? 1.f : 0.f;

    float fE = 0.f, fO1 = 0.f, fO2 = 0.f;   // S values of row 127 (final)

    for (int g = 0; g < T_ / 4; ++g) {
        mbar_wait0(smem_u32(&mbar[g]));
        // load S for rows 4g..4g+3 (independent LDS, overlap)
        float sE[4], sO1[4], sO2[4];
#pragma unroll
        for (int k = 0; k < 4; ++k) {
            const int r = 4 * g + k;
            sE[k]  = S_sh[r][0];
            sO1[k] = S_sh[r][cO1];
            sO2[k] = S_sh[r][cO2];
        }
#pragma unroll
        for (int k = 0; k < 4; ++k) {
            const int r = 4 * g + k;
            if (r == 127) { fE = sE[k]; fO1 = sO1[k]; fO2 = sO2[k]; break; }
            const int cc_t = cc_sh[r + 1];

            // e = max(P*S, TINY); unreachable -> TINY
            float e[5];
            e[0] = fmaxf(P[0] * sE[k],  MINF);
            e[1] = fmaxf(P[1] * sO1[k], MINF);
            e[2] = fmaxf(P[2] * sE[k],  MINF);
            e[3] = fmaxf(P[3] * sO2[k], MINF);
            e[4] = fmaxf(P[4] * sE[k],  MINF);
#pragma unroll
            for (int i = 0; i < 5; ++i)
                if (sB + i > cc_t) e[i] = MINF;

            const float em1 = __shfl_up_sync(0xffffffffu, e[3], 1);
            const float em2 = __shfl_up_sync(0xffffffffu, e[2], 1);

            float Pn[5];
            Pn[0] = (lane == 0) ? e[0] : e[0] + em1 + (skipb[0] ? em2 : 0.f);
            Pn[1] = e[1] + e[0] + (skipb[1] ? em1 : 0.f);
#pragma unroll
            for (int i = 2; i < 5; ++i)
                Pn[i] = e[i] + e[i - 1] + (skipb[i] ? e[i - 2] : 0.f);
#pragma unroll
            for (int i = 0; i < 5; ++i) P[i] = Pn[i];
        }
    }

    // final: res2[s] = lg2(P[s]) + lg2(S127[col]) (log domain; avoids
    // subnormal/FTZ loss in the unclamped final stage)
    const float lE  = lg2f(fE), lO1 = lg2f(fO1), lO2 = lg2f(fO2);
    res_sh[sB + 0] = lg2f(P[0]) + lE;
    res_sh[sB + 1] = lg2f(P[1]) + lO1;
    res_sh[sB + 2] = lg2f(P[2]) + lE;
    res_sh[sB + 3] = lg2f(P[3]) + lO2;
    if (lane == 31) res_sh[128] = lg2f(P[4]) + lE;
    __syncwarp();

    if (lane == 0) {
        const int   L = 2 * tlen[n] + 1;
        const float x = res_sh[L - 1], y = res_sh[L - 2];
        const float mx = fmaxf(x, y);
        const float l2 = mx + lg2f(ex2f(x - mx) + ex2f(y - mx));
        out[n] = -((LN2 * l2) / (float)tlen[n]);
    }
}

} // anonymous namespace

extern "C" void kernel_launch(void* const* d_in, const int* /*in_sizes*/, int /*n_in*/,
                              void* d_out, int /*out_size*/) {
    const float* mask     = (const float*)d_in[0];
    const float* classify = (const float*)d_in[1];
    const int*   targets  = (const int*)d_in[2];
    // d_in[3] = input_lengths (always T, unused)
    const int*   tlen     = (const int*)d_in[4];

    fused_kernel<<<2 * N_, 512>>>(mask, classify, targets, tlen, (float*)d_out);
}

// round 13
// speedup vs baseline: 1.4620x; 1.2783x over previous
#include <cuda_runtime.h>
#include <cstdint>

namespace {

constexpr int T_ = 128, H_ = 16, N_ = 64, C_ = 256, S_ = 129;
constexpr int NC_ = N_ * C_;
constexpr int NPROD = 31;          // producers per n: 15 (rank0) + 16 (rank1)

constexpr float L2E  = 1.4426950408889634f;
constexpr float LN2  = 0.6931471805599453f;
constexpr float MINF = 1.17549435e-38f;        // 2^-126 == FLT_MIN == TINY

__device__ __forceinline__ float ex2f(float x) { float y; asm("ex2.approx.f32 %0, %1;" : "=f"(y) : "f"(x)); return y; }
__device__ __forceinline__ float lg2f(float x) { float y; asm("lg2.approx.f32 %0, %1;" : "=f"(y) : "f"(x)); return y; }

__device__ __forceinline__ uint32_t smem_u32(const void* p) {
    uint32_t a;
    asm("{ .reg .u64 t; cvta.to.shared.u64 t, %1; cvt.u32.u64 %0, t; }" : "=r"(a) : "l"(p));
    return a;
}
__device__ __forceinline__ uint32_t mapa_rank0(uint32_t local) {
    uint32_t r;
    asm("mapa.shared::cluster.u32 %0, %1, 0;" : "=r"(r) : "r"(local));
    return r;
}
__device__ __forceinline__ void st_cl_f32(uint32_t a, float v) {
    asm volatile("st.shared::cluster.f32 [%0], %1;" :: "r"(a), "f"(v));
}
__device__ __forceinline__ void mbar_init(uint32_t a, unsigned cnt) {
    asm volatile("mbarrier.init.shared.b64 [%0], %1;" :: "r"(a), "r"(cnt) : "memory");
}
__device__ __forceinline__ void mbar_arrive_cluster(uint32_t mapped) {
    asm volatile("mbarrier.arrive.release.cluster.shared::cluster.b64 _, [%0];"
                 :: "r"(mapped) : "memory");
}
__device__ __forceinline__ void mbar_wait0(uint32_t a) {
    uint32_t done;
    asm volatile(
        "{\n\t.reg .pred p;\n\t"
        "mbarrier.try_wait.parity.acquire.cta.shared::cta.b64 p, [%1], 0;\n\t"
        "selp.b32 %0, 1, 0, p;\n\t}"
        : "=r"(done) : "r"(a) : "memory");
    if (!done) {
        asm volatile(
            "{\n\t.reg .pred P1;\n\t"
            "WL_%=:\n\t"
            "mbarrier.try_wait.parity.acquire.cta.shared::cta.b64 P1, [%0], 0, 0x989680;\n\t"
            "@P1 bra.uni WD_%=;\n\t"
            "bra.uni WL_%=;\n\t"
            "WD_%=:\n\t}"
            :: "r"(a) : "memory");
    }
}
__device__ __forceinline__ void cluster_sync() {
    asm volatile("barrier.cluster.arrive.aligned;" ::: "memory");
    asm volatile("barrier.cluster.wait.aligned;" ::: "memory");
}
__device__ __forceinline__ uint32_t ctarank() {
    uint32_t r; asm("mov.u32 %0, %%cluster_ctarank;" : "=r"(r)); return r;
}

// 2-CTA cluster per n, 512 threads/CTA. Rank0: 15 producer warps + consumer
// warp 15; rank1: 16 producers. Producers gather ONLY the 65 deduped columns,
// with column->lane assignment SORTED by column value so each of the two
// 32-lane gathers covers a contiguous address span (minimal L1tex sector
// wavefronts). Linear S[t][c] = sum_h 2^(cls+m) written to rank0 smem via
// DSMEM at the ORIGINAL column index; release-arrive on group-of-4 mbarriers.
// Consumer: linear-domain CTC recurrence (e = max(P*S, TINY)).
__global__ __launch_bounds__(512, 1) __cluster_dims__(2, 1, 1)
void fused_kernel(
    const float* __restrict__ mask,      // [T,H,N]
    const float* __restrict__ classify,  // [T,H,N,C]
    const int*   __restrict__ targets,   // [N,64]
    const int*   __restrict__ tlen,      // [N]
    float* __restrict__ out)             // [N]
{
    __shared__ float    S_sh[T_][68];    // linear per-column h-sums
    __shared__ uint64_t mbar[T_ / 4];    // one barrier per 4-row group
    __shared__ int      tgt_sh[64];
    __shared__ int      cc_sh[T_];
    __shared__ float    res_sh[S_];
    __shared__ int      colv_sh[65];     // entry -> column value
    __shared__ int      scol_sh[65];     // rank  -> column value (sorted)
    __shared__ int      sidx_sh[65];     // rank  -> original entry index

    const int n    = blockIdx.x >> 1;
    const int rank = (int)ctarank();
    const int tid  = threadIdx.x;
    const int w    = tid >> 5;
    const int lane = tid & 31;

    if (rank == 0 && tid < T_ / 4) mbar_init(smem_u32(&mbar[tid]), 128);
    if (tid < 64) tgt_sh[tid] = targets[n * 64 + tid];
    __syncthreads();

    // entry c (0..64): column value (blank=0 for c=0, else targets[c-1])
    if (tid < 65) colv_sh[tid] = (tid == 0) ? 0 : tgt_sh[tid - 1];
    __syncthreads();
    // warp-parallel rank sort (ties broken by index -> rank is a permutation)
    if (tid < 65) {
        const int v = colv_sh[tid];
        int r = 0;
        for (int j = 0; j < 65; ++j) {
            const int u = colv_sh[j];
            r += (u < v) || (u == v && j < tid);
        }
        scol_sh[r] = v;
        sidx_sh[r] = tid;
    }
    __syncthreads();
    cluster_sync();                 // barriers + tables live before producing

    const bool isProd = (rank == 1) || (w < 15);

    if (isProd) {
        // ======================= producer warp =======================
        const int pid = (rank == 0) ? w : (15 + w);   // 0..30
        // sorted assignment: lane -> sorted ranks l and 32+l; lane31 also 64
        const int sc1 = scol_sh[lane],      oi1 = sidx_sh[lane];
        const int sc2 = scol_sh[32 + lane], oi2 = sidx_sh[32 + lane];
        const int sc3 = scol_sh[64],        oi3 = sidx_sh[64];
        const size_t b1 = (size_t)n * C_ + sc1;
        const size_t b2 = (size_t)n * C_ + sc2;
        const size_t b3 = (size_t)n * C_ + sc3;
        const bool   l31 = (lane == 31);

        for (int t = pid; t < T_; t += NPROD) {
            const float* base = classify + (size_t)t * H_ * NC_;
            const float  m = (lane < 16)
                ? __ldg(&mask[((size_t)t * H_ + lane) * N_ + n]) * L2E : 0.f;

            // issue all gathers up front (full MLP)
            float v1[H_], v2[H_], v3[H_];
#pragma unroll
            for (int h = 0; h < H_; ++h) {
                const size_t ho = (size_t)h * NC_;
                v1[h] = __ldg(base + ho + b1);
                v2[h] = __ldg(base + ho + b2);
            }
            if (l31) {
#pragma unroll
                for (int h = 0; h < H_; ++h) v3[h] = __ldg(base + (size_t)h * NC_ + b3);
            }

            float s1 = 0.f, s2 = 0.f, s3 = 0.f;
#pragma unroll
            for (int h = 0; h < H_; ++h) {
                const float mh = __shfl_sync(0xffffffffu, m, h);
                s1 += ex2f(__fmaf_rn(v1[h], L2E, mh));
                s2 += ex2f(__fmaf_rn(v2[h], L2E, mh));
                if (l31) s3 += ex2f(__fmaf_rn(v3[h], L2E, mh));
            }

            // write linear sums at ORIGINAL column indices into rank0's S_sh
            const uint32_t r0 = mapa_rank0(smem_u32(&S_sh[t][0]));
            st_cl_f32(r0 + 4u * oi1, s1);
            st_cl_f32(r0 + 4u * oi2, s2);
            if (l31) st_cl_f32(r0 + 4u * oi3, s3);
            mbar_arrive_cluster(mapa_rank0(smem_u32(&mbar[t >> 2])));
        }
        return;
    }

    // =================== consumer warp (rank0, w == 15) ===================
    const int NS = (lane == 31) ? 5 : 4;
    const int sB = 4 * lane;

    // cc prefix scan (reachability frontier)
    {
        int c[4], pfx = 0;
#pragma unroll
        for (int i = 0; i < 4; ++i) {
            int u = 4 * lane + i, v = 0;
            if (u >= 2) {
                int sk = 0;
                if ((u & 1) && u >= 3) sk = (tgt_sh[(u - 1) >> 1] != tgt_sh[(u - 3) >> 1]);
                v = sk + 1;
            }
            pfx += v; c[i] = pfx;
        }
        int tot = pfx;
#pragma unroll
        for (int d = 1; d < 32; d <<= 1) {
            int up = __shfl_up_sync(0xffffffffu, tot, d);
            if (lane >= d) tot += up;
        }
        int excl = tot - pfx;
#pragma unroll
        for (int i = 0; i < 4; ++i) {
            int u = 4 * lane + i;
            if (u >= 1) cc_sh[u] = 2 + excl + c[i];
        }
    }
    __syncwarp();

    bool skipb[5];
#pragma unroll
    for (int i = 0; i < 5; ++i) {
        int s = sB + i;
        skipb[i] = (i < NS) && (s & 1) && (s >= 3) &&
                   (tgt_sh[(s - 1) >> 1] != tgt_sh[(s - 3) >> 1]);
    }

    const int cO1 = 2 * lane + 1;   // col of state 4l+1
    const int cO2 = 2 * lane + 2;   // col of state 4l+3

    // linear-domain state: P[i] = 2^np[i]
    float P[5];
#pragma unroll
    for (int i = 0; i < 5; ++i) P[i] = (sB + i < 2) ? 1.f : 0.f;

    float fE = 0.f, fO1 = 0.f, fO2 = 0.f;   // S values of row 127 (final)

    for (int g = 0; g < T_ / 4; ++g) {
        mbar_wait0(smem_u32(&mbar[g]));
        float sE[4], sO1[4], sO2[4];
#pragma unroll
        for (int k = 0; k < 4; ++k) {
            const int r = 4 * g + k;
            sE[k]  = S_sh[r][0];
            sO1[k] = S_sh[r][cO1];
            sO2[k] = S_sh[r][cO2];
        }
#pragma unroll
        for (int k = 0; k < 4; ++k) {
            const int r = 4 * g + k;
            if (r == 127) { fE = sE[k]; fO1 = sO1[k]; fO2 = sO2[k]; break; }
            const int cc_t = cc_sh[r + 1];

            // e = max(P*S, TINY); unreachable -> TINY
            float e[5];
            e[0] = fmaxf(P[0] * sE[k],  MINF);
            e[1] = fmaxf(P[1] * sO1[k], MINF);
            e[2] = fmaxf(P[2] * sE[k],  MINF);
            e[3] = fmaxf(P[3] * sO2[k], MINF);
            e[4] = fmaxf(P[4] * sE[k],  MINF);
#pragma unroll
            for (int i = 0; i < 5; ++i)
                if (sB + i > cc_t) e[i] = MINF;

            const float em1 = __shfl_up_sync(0xffffffffu, e[3], 1);
            const float em2 = __shfl_up_sync(0xffffffffu, e[2], 1);

            float Pn[5];
            Pn[0] = (lane == 0) ? e[0] : e[0] + em1 + (skipb[0] ? em2 : 0.f);
            Pn[1] = e[1] + e[0] + (skipb[1] ? em1 : 0.f);
#pragma unroll
            for (int i = 2; i < 5; ++i)
                Pn[i] = e[i] + e[i - 1] + (skipb[i] ? e[i - 2] : 0.f);
#pragma unroll
            for (int i = 0; i < 5; ++i) P[i] = Pn[i];
        }
    }

    // final: res2[s] = lg2(P[s]) + lg2(S127[col])
    const float lE  = lg2f(fE), lO1 = lg2f(fO1), lO2 = lg2f(fO2);
    res_sh[sB + 0] = lg2f(P[0]) + lE;
    res_sh[sB + 1] = lg2f(P[1]) + lO1;
    res_sh[sB + 2] = lg2f(P[2]) + lE;
    res_sh[sB + 3] = lg2f(P[3]) + lO2;
    if (lane == 31) res_sh[128] = lg2f(P[4]) + lE;
    __syncwarp();

    if (lane == 0) {
        const int   L = 2 * tlen[n] + 1;
        const float x = res_sh[L - 1], y = res_sh[L - 2];
        const float mx = fmaxf(x, y);
        const float l2 = mx + lg2f(ex2f(x - mx) + ex2f(y - mx));
        out[n] = -((LN2 * l2) / (float)tlen[n]);
    }
}

} // anonymous namespace

extern "C" void kernel_launch(void* const* d_in, const int* /*in_sizes*/, int /*n_in*/,
                              void* d_out, int /*out_size*/) {
    const float* mask     = (const float*)d_in[0];
    const float* classify = (const float*)d_in[1];
    const int*   targets  = (const int*)d_in[2];
    // d_in[3] = input_lengths (always T, unused)
    const int*   tlen     = (const int*)d_in[4];

    fused_kernel<<<2 * N_, 512>>>(mask, classify, targets, tlen, (float*)d_out);
}